// round 14
// baseline (speedup 1.0000x reference)
#include <cuda_runtime.h>
#include <cuda_bf16.h>
#include <cstdint>

// Problem constants
#define B 4
#define C 4
#define H 256
#define W 256
#define HW (H*W)          // 65536
#define FS 11
#define PAD 5

// Tile config: one pixel per thread
#define BW 32             // tile width
#define BH 8              // tile height
#define NTHREADS 256      // BW * BH
#define HALO_W (BW + FS - 1)   // 42
#define HALO_H (BH + FS - 1)   // 18
#define NHALO (HALO_H * HALO_W)  // 756
#define NHIT ((NHALO + NTHREADS - 1) / NTHREADS)   // 3
#define SST 43            // shared row stride in float4 (bank-skewed)

__device__ __forceinline__ float ex2(float s) {
    float r;
    asm("ex2.approx.f32 %0, %1;" : "=f"(r) : "f"(s));
    return r;
}

// ---------------------------------------------------------------------------
// Single fused kernel, algebraically folded:
//   score_k = psi . x_k   with  psi = (Wp^T Wt) x_p  (pre-scaled by log2 e)
//   out     = M (sum_k att_k x_k) + x,  M = Ww Wg
// ONE pixel per thread (max resident warps), all-scalar, fully unrolled.
// ---------------------------------------------------------------------------
__global__ __launch_bounds__(NTHREADS, 7) void fused_kernel(
    const float* __restrict__ x,
    const float* __restrict__ Wt,
    const float* __restrict__ Wp,
    const float* __restrict__ Wg,
    const float* __restrict__ Ww,
    float* __restrict__ out)
{
    __shared__ float4 xsh[HALO_H * SST];   // x halo: (c0,c1,c2,c3) per pixel
    __shared__ float wN[16];               // N = Wp^T Wt, scaled by log2 e
    __shared__ float wM[16];               // M = Ww Wg

    int tid = threadIdx.x;

    int b  = blockIdx.z;
    int h0 = blockIdx.y * BH;
    int w0 = blockIdx.x * BW;
    const float* xb = x + b * (C * HW);

    // --- Small matrix products N, M (threads 0..31, one entry each) ---
    if (tid < 32) {
        int e = tid & 15;
        int i = e >> 2;       // row
        int j = e & 3;        // col
        if (tid < 16) {
            float s = Wp[i] * Wt[j];
            s = fmaf(Wp[4 + i],  Wt[4 + j],  s);
            s = fmaf(Wp[8 + i],  Wt[8 + j],  s);
            s = fmaf(Wp[12 + i], Wt[12 + j], s);
            wN[e] = s * 1.4426950408889634f;
        } else {
            float s = Ww[i*4 + 0] * Wg[j];
            s = fmaf(Ww[i*4 + 1], Wg[4 + j],  s);
            s = fmaf(Ww[i*4 + 2], Wg[8 + j],  s);
            s = fmaf(Ww[i*4 + 3], Wg[12 + j], s);
            wM[e] = s;
        }
    }

    // --- Halo: batch ALL global loads first (MLP), then shared stores ---
    float v0[NHIT], v1[NHIT], v2[NHIT], v3[NHIT];
    #pragma unroll
    for (int it = 0; it < NHIT; it++) {
        int idx = it * NTHREADS + tid;
        v0[it] = 0.f; v1[it] = 0.f; v2[it] = 0.f; v3[it] = 0.f;
        if (idx < NHALO) {
            int i  = idx / HALO_W;
            int j  = idx - i * HALO_W;
            int gh = h0 - PAD + i;
            int gw = w0 - PAD + j;
            if ((unsigned)gh < (unsigned)H && (unsigned)gw < (unsigned)W) {
                const float* xp = xb + gh * W + gw;
                v0[it] = xp[0];
                v1[it] = xp[HW];
                v2[it] = xp[2*HW];
                v3[it] = xp[3*HW];
            }
        }
    }
    #pragma unroll
    for (int it = 0; it < NHIT; it++) {
        int idx = it * NTHREADS + tid;
        if (idx < NHALO) {
            int i  = idx / HALO_W;
            int j  = idx - i * HALO_W;
            xsh[i * SST + j] = make_float4(v0[it], v1[it], v2[it], v3[it]);
        }
    }
    __syncthreads();

    // --- Pixel mapping: warp = one image row (conflict-free, coalesced) ---
    int tx = tid & 31;
    int ty = tid >> 5;

    // Own pixel from shared halo (saves global loads + live registers)
    int ownidx = (ty + PAD) * SST + (tx + PAD);
    float4 Xo = xsh[ownidx];

    // psi = N x_p (scaled by log2 e)
    float p0 = fmaf(wN[0],  Xo.x, fmaf(wN[1],  Xo.y, fmaf(wN[2],  Xo.z, wN[3]  * Xo.w)));
    float p1 = fmaf(wN[4],  Xo.x, fmaf(wN[5],  Xo.y, fmaf(wN[6],  Xo.z, wN[7]  * Xo.w)));
    float p2 = fmaf(wN[8],  Xo.x, fmaf(wN[9],  Xo.y, fmaf(wN[10], Xo.z, wN[11] * Xo.w)));
    float p3 = fmaf(wN[12], Xo.x, fmaf(wN[13], Xo.y, fmaf(wN[14], Xo.z, wN[15] * Xo.w)));

    float acc0 = 0.f, acc1 = 0.f, acc2 = 0.f, acc3 = 0.f, sum = 0.f;

    // --- Main loop: FULLY UNROLLED 11x11, direct indexed LDS.128 ---
    int base = ty * SST + tx;
    #pragma unroll
    for (int ki = 0; ki < FS; ki++) {
        const float4* row = &xsh[base + ki * SST];
        #pragma unroll
        for (int kj = 0; kj < FS; kj++) {
            float4 X = row[kj];
            float s = fmaf(p0, X.x,
                      fmaf(p1, X.y,
                      fmaf(p2, X.z, p3 * X.w)));
            float e = ex2(s);       // psi pre-scaled by log2 e
            sum += e;
            acc0 = fmaf(e, X.x, acc0);
            acc1 = fmaf(e, X.y, acc1);
            acc2 = fmaf(e, X.z, acc2);
            acc3 = fmaf(e, X.w, acc3);
        }
    }

    // --- Epilogue: normalize, apply M, add residual (re-read own x) ---
    float inv = __frcp_rn(sum);
    float a0 = acc0 * inv;
    float a1 = acc1 * inv;
    float a2 = acc2 * inv;
    float a3 = acc3 * inv;

    int pix = (h0 + ty) * W + (w0 + tx);
    float* ob = out + b * (C * HW);
    float4 Xr = xsh[ownidx];
    ob[0*HW + pix] = fmaf(wM[0],  a0, fmaf(wM[1],  a1, fmaf(wM[2],  a2, wM[3]  * a3))) + Xr.x;
    ob[1*HW + pix] = fmaf(wM[4],  a0, fmaf(wM[5],  a1, fmaf(wM[6],  a2, wM[7]  * a3))) + Xr.y;
    ob[2*HW + pix] = fmaf(wM[8],  a0, fmaf(wM[9],  a1, fmaf(wM[10], a2, wM[11] * a3))) + Xr.z;
    ob[3*HW + pix] = fmaf(wM[12], a0, fmaf(wM[13], a1, fmaf(wM[14], a2, wM[15] * a3))) + Xr.w;
}

// ---------------------------------------------------------------------------
extern "C" void kernel_launch(void* const* d_in, const int* in_sizes, int n_in,
                              void* d_out, int out_size)
{
    const float* x  = (const float*)d_in[0];
    const float* Wt = (const float*)d_in[1];
    const float* Wp = (const float*)d_in[2];
    const float* Wg = (const float*)d_in[3];
    const float* Ww = (const float*)d_in[4];
    float* out = (float*)d_out;

    dim3 grid(W / BW, H / BH, B);
    fused_kernel<<<grid, NTHREADS>>>(x, Wt, Wp, Wg, Ww, out);
}

// round 15
// speedup vs baseline: 1.0236x; 1.0236x over previous
#include <cuda_runtime.h>
#include <cuda_bf16.h>
#include <cstdint>

// Problem constants
#define B 4
#define C 4
#define H 256
#define W 256
#define HW (H*W)          // 65536
#define FS 11
#define PAD 5

// Tile config
#define BW 32             // tile width (output pixels)
#define BH 8              // tile height
#define R  2              // pixels per thread along w
#define NTHREADS 128      // (BW/R) * BH = 16 * 8
#define HALO_W (BW + FS - 1)   // 42
#define HALO_H (BH + FS - 1)   // 18
#define NHALO (HALO_H * HALO_W)  // 756
#define NHIT ((NHALO + NTHREADS - 1) / NTHREADS)   // 6
#define SST 43            // shared row stride in 16B units (bank-skewed)

__device__ __forceinline__ float ex2(float s) {
    float r;
    asm("ex2.approx.f32 %0, %1;" : "=f"(r) : "f"(s));
    return r;
}

// ---------------------------------------------------------------------------
// Single fused kernel, algebraically folded:
//   score_k = psi . x_k   with  psi = (Wp^T Wt) x_p  (pre-scaled by log2 e)
//   out     = M (sum_k att_k x_k) + x,  M = Ww Wg
// ALL-SCALAR arithmetic, fully-unrolled 11x11 loop.
// Halo fill INTERLEAVED (LDG burst of 4 -> STS) to keep MLP_p1 low and avoid
// cross-CTA L1tex-queue spread at high occupancy.
// ---------------------------------------------------------------------------
__global__ __launch_bounds__(NTHREADS, 7) void fused_kernel(
    const float* __restrict__ x,
    const float* __restrict__ Wt,
    const float* __restrict__ Wp,
    const float* __restrict__ Wg,
    const float* __restrict__ Ww,
    float* __restrict__ out)
{
    __shared__ float4 xsh[HALO_H * SST];   // x halo: (c0,c1,c2,c3) per pixel
    __shared__ float wN[16];               // N = Wp^T Wt, scaled by log2 e
    __shared__ float wM[16];               // M = Ww Wg

    int tid = threadIdx.x;

    int b  = blockIdx.z;
    int h0 = blockIdx.y * BH;
    int w0 = blockIdx.x * BW;
    const float* xb = x + b * (C * HW);

    // --- Small matrix products N, M (threads 0..31, one entry each) ---
    if (tid < 32) {
        int e = tid & 15;
        int i = e >> 2;       // row
        int j = e & 3;        // col
        if (tid < 16) {
            float s = Wp[i] * Wt[j];
            s = fmaf(Wp[4 + i],  Wt[4 + j],  s);
            s = fmaf(Wp[8 + i],  Wt[8 + j],  s);
            s = fmaf(Wp[12 + i], Wt[12 + j], s);
            wN[e] = s * 1.4426950408889634f;
        } else {
            float s = Ww[i*4 + 0] * Wg[j];
            s = fmaf(Ww[i*4 + 1], Wg[4 + j],  s);
            s = fmaf(Ww[i*4 + 2], Wg[8 + j],  s);
            s = fmaf(Ww[i*4 + 3], Wg[12 + j], s);
            wM[e] = s;
        }
    }

    // --- Halo fill: per-iteration LDG(4)->STS (low MLP_p1, no batching) ---
    #pragma unroll 1
    for (int it = 0; it < NHIT; it++) {
        int idx = it * NTHREADS + tid;
        if (idx < NHALO) {
            int i  = idx / HALO_W;
            int j  = idx - i * HALO_W;
            int gh = h0 - PAD + i;
            int gw = w0 - PAD + j;
            float4 v = make_float4(0.f, 0.f, 0.f, 0.f);
            if ((unsigned)gh < (unsigned)H && (unsigned)gw < (unsigned)W) {
                const float* xp = xb + gh * W + gw;
                v = make_float4(xp[0], xp[HW], xp[2*HW], xp[3*HW]);
            }
            xsh[i * SST + j] = v;
        }
    }

    // --- Own-pixel x loads (for psi and residual) ---
    // Lane mapping: ty = lane&1 (+2 per warp), tx = (lane>>1)&15.
    // Conflict-free 8-lane LDS.128 phases given SST=43.
    int tx = (tid >> 1) & 15;
    int ty = ((tid >> 5) << 1) | (tid & 1);
    int oh = h0 + ty;
    int ow = w0 + tx * R;
    int pixbase = oh * W + ow;

    float xs[4][R];
    #pragma unroll
    for (int c = 0; c < 4; c++) {
        float2 v = *(const float2*)(xb + c * HW + pixbase);
        xs[c][0] = v.x; xs[c][1] = v.y;
    }
    __syncthreads();

    // --- psi = N x_p (per own pixel), scalar ---
    float p0[R], p1[R], p2[R], p3[R];
    float acc0[R], acc1[R], acc2[R], acc3[R], sum[R];
    #pragma unroll
    for (int r = 0; r < R; r++) {
        p0[r] = fmaf(wN[0],  xs[0][r], fmaf(wN[1],  xs[1][r], fmaf(wN[2],  xs[2][r], wN[3]  * xs[3][r])));
        p1[r] = fmaf(wN[4],  xs[0][r], fmaf(wN[5],  xs[1][r], fmaf(wN[6],  xs[2][r], wN[7]  * xs[3][r])));
        p2[r] = fmaf(wN[8],  xs[0][r], fmaf(wN[9],  xs[1][r], fmaf(wN[10], xs[2][r], wN[11] * xs[3][r])));
        p3[r] = fmaf(wN[12], xs[0][r], fmaf(wN[13], xs[1][r], fmaf(wN[14], xs[2][r], wN[15] * xs[3][r])));
        acc0[r] = 0.f; acc1[r] = 0.f; acc2[r] = 0.f; acc3[r] = 0.f;
        sum[r] = 0.f;
    }

    int base = ty * SST + tx * R;

    // --- Main loop: FULLY UNROLLED 11 rows x 11 cols, all scalar ---
    #pragma unroll
    for (int ki = 0; ki < FS; ki++) {
        const float4* row = &xsh[base + ki * SST];
        float4 xw[4];
        xw[0] = row[0]; xw[1] = row[1]; xw[2] = row[2];
        #pragma unroll
        for (int kj = 0; kj < FS; kj++) {
            if (kj < 9) xw[(kj + 3) & 3] = row[kj + 3];   // compile-time guard
            #pragma unroll
            for (int r = 0; r < R; r++) {
                float4 X = xw[(kj + r) & 3];
                float s = fmaf(p0[r], X.x,
                          fmaf(p1[r], X.y,
                          fmaf(p2[r], X.z, p3[r] * X.w)));
                float e = ex2(s);       // psi pre-scaled by log2 e
                sum[r] += e;
                acc0[r] = fmaf(e, X.x, acc0[r]);
                acc1[r] = fmaf(e, X.y, acc1[r]);
                acc2[r] = fmaf(e, X.z, acc2[r]);
                acc3[r] = fmaf(e, X.w, acc3[r]);
            }
        }
    }

    // --- Epilogue: normalize, apply M, residual; float2 stores ---
    float a0[R], a1[R], a2[R], a3[R];
    #pragma unroll
    for (int r = 0; r < R; r++) {
        float inv = __frcp_rn(sum[r]);
        a0[r] = acc0[r] * inv;
        a1[r] = acc1[r] * inv;
        a2[r] = acc2[r] * inv;
        a3[r] = acc3[r] * inv;
    }
    float* ob = out + b * (C * HW);
    #pragma unroll
    for (int c = 0; c < C; c++) {
        float2 res;
        res.x = fmaf(wM[c*4+0], a0[0], fmaf(wM[c*4+1], a1[0], fmaf(wM[c*4+2], a2[0], wM[c*4+3] * a3[0]))) + xs[c][0];
        res.y = fmaf(wM[c*4+0], a0[1], fmaf(wM[c*4+1], a1[1], fmaf(wM[c*4+2], a2[1], wM[c*4+3] * a3[1]))) + xs[c][1];
        *(float2*)(ob + c * HW + pixbase) = res;
    }
}

// ---------------------------------------------------------------------------
extern "C" void kernel_launch(void* const* d_in, const int* in_sizes, int n_in,
                              void* d_out, int out_size)
{
    const float* x  = (const float*)d_in[0];
    const float* Wt = (const float*)d_in[1];
    const float* Wp = (const float*)d_in[2];
    const float* Wg = (const float*)d_in[3];
    const float* Ww = (const float*)d_in[4];
    float* out = (float*)d_out;

    dim3 grid(W / BW, H / BH, B);
    fused_kernel<<<grid, NTHREADS>>>(x, Wt, Wp, Wg, Ww, out);
}

// round 16
// speedup vs baseline: 1.0410x; 1.0170x over previous
#include <cuda_runtime.h>
#include <cuda_bf16.h>
#include <cstdint>

// Problem constants
#define B 4
#define C 4
#define H 256
#define W 256
#define HW (H*W)          // 65536
#define FS 11
#define PAD 5

// Tile config
#define BW 32             // tile width (output pixels)
#define BH 8              // tile height
#define R  2              // pixels per thread along w
#define NTHREADS 128      // (BW/R) * BH = 16 * 8
#define HALO_W (BW + FS - 1)   // 42
#define HALO_H (BH + FS - 1)   // 18
#define NHALO (HALO_H * HALO_W)  // 756
#define NHIT ((NHALO + NTHREADS - 1) / NTHREADS)   // 6
#define SST 43            // shared row stride in float4 (bank-skewed)

__device__ __forceinline__ float ex2(float s) {
    float r;
    asm("ex2.approx.f32 %0, %1;" : "=f"(r) : "f"(s));
    return r;
}

// ---------------------------------------------------------------------------
// Single fused kernel, algebraically folded:
//   score_k = psi . x_k   with  psi = (Wp^T Wt) x_p  (pre-scaled by log2 e)
//   out     = M (sum_k att_k x_k) + x,  M = Ww Wg
// ALL-SCALAR arithmetic, fully-unrolled 11x11 loop, batched halo LDG.
// Own-pixel values re-read from the shared halo (no extra global loads).
// ---------------------------------------------------------------------------
__global__ __launch_bounds__(NTHREADS, 7) void fused_kernel(
    const float* __restrict__ x,
    const float* __restrict__ Wt,
    const float* __restrict__ Wp,
    const float* __restrict__ Wg,
    const float* __restrict__ Ww,
    float* __restrict__ out)
{
    __shared__ float4 xsh[HALO_H * SST];   // x halo: (c0,c1,c2,c3) per pixel
    __shared__ float wN[16];               // N = Wp^T Wt, scaled by log2 e
    __shared__ float wM[16];               // M = Ww Wg

    int tid = threadIdx.x;

    int b  = blockIdx.z;
    int h0 = blockIdx.y * BH;
    int w0 = blockIdx.x * BW;
    const float* xb = x + b * (C * HW);

    // --- Small matrix products N, M (threads 0..31, one entry each) ---
    if (tid < 32) {
        int e = tid & 15;
        int i = e >> 2;       // row
        int j = e & 3;        // col
        if (tid < 16) {
            float s = Wp[i] * Wt[j];
            s = fmaf(Wp[4 + i],  Wt[4 + j],  s);
            s = fmaf(Wp[8 + i],  Wt[8 + j],  s);
            s = fmaf(Wp[12 + i], Wt[12 + j], s);
            wN[e] = s * 1.4426950408889634f;
        } else {
            float s = Ww[i*4 + 0] * Wg[j];
            s = fmaf(Ww[i*4 + 1], Wg[4 + j],  s);
            s = fmaf(Ww[i*4 + 2], Wg[8 + j],  s);
            s = fmaf(Ww[i*4 + 3], Wg[12 + j], s);
            wM[e] = s;
        }
    }

    // --- Halo: batch ALL global loads first (MLP), then shared stores ---
    float v0[NHIT], v1[NHIT], v2[NHIT], v3[NHIT];
    #pragma unroll
    for (int it = 0; it < NHIT; it++) {
        int idx = it * NTHREADS + tid;
        v0[it] = 0.f; v1[it] = 0.f; v2[it] = 0.f; v3[it] = 0.f;
        if (idx < NHALO) {
            int i  = idx / HALO_W;
            int j  = idx - i * HALO_W;
            int gh = h0 - PAD + i;
            int gw = w0 - PAD + j;
            if ((unsigned)gh < (unsigned)H && (unsigned)gw < (unsigned)W) {
                const float* xp = xb + gh * W + gw;
                v0[it] = xp[0];
                v1[it] = xp[HW];
                v2[it] = xp[2*HW];
                v3[it] = xp[3*HW];
            }
        }
    }
    #pragma unroll
    for (int it = 0; it < NHIT; it++) {
        int idx = it * NTHREADS + tid;
        if (idx < NHALO) {
            int i  = idx / HALO_W;
            int j  = idx - i * HALO_W;
            xsh[i * SST + j] = make_float4(v0[it], v1[it], v2[it], v3[it]);
        }
    }
    __syncthreads();

    // --- Lane mapping: ty = lane&1 (+2 per warp), tx = (lane>>1)&15.
    // Conflict-free 8-lane LDS.128 phases given SST=43.
    int tx = (tid >> 1) & 15;
    int ty = ((tid >> 5) << 1) | (tid & 1);
    int pixbase = (h0 + ty) * W + (w0 + tx * R);

    // Own-pixel x from the shared halo (saves 8 global loads per thread)
    int ownoff = (ty + PAD) * SST + (PAD + tx * R);
    float4 Xo0 = xsh[ownoff];
    float4 Xo1 = xsh[ownoff + 1];
    float xs[4][R] = { { Xo0.x, Xo1.x }, { Xo0.y, Xo1.y },
                       { Xo0.z, Xo1.z }, { Xo0.w, Xo1.w } };

    // --- psi = N x_p (per own pixel), scalar ---
    float p0[R], p1[R], p2[R], p3[R];
    float acc0[R], acc1[R], acc2[R], acc3[R], sum[R];
    #pragma unroll
    for (int r = 0; r < R; r++) {
        p0[r] = fmaf(wN[0],  xs[0][r], fmaf(wN[1],  xs[1][r], fmaf(wN[2],  xs[2][r], wN[3]  * xs[3][r])));
        p1[r] = fmaf(wN[4],  xs[0][r], fmaf(wN[5],  xs[1][r], fmaf(wN[6],  xs[2][r], wN[7]  * xs[3][r])));
        p2[r] = fmaf(wN[8],  xs[0][r], fmaf(wN[9],  xs[1][r], fmaf(wN[10], xs[2][r], wN[11] * xs[3][r])));
        p3[r] = fmaf(wN[12], xs[0][r], fmaf(wN[13], xs[1][r], fmaf(wN[14], xs[2][r], wN[15] * xs[3][r])));
        acc0[r] = 0.f; acc1[r] = 0.f; acc2[r] = 0.f; acc3[r] = 0.f;
        sum[r] = 0.f;
    }

    int base = ty * SST + tx * R;

    // --- Main loop: FULLY UNROLLED 11 rows x 11 cols, all scalar ---
    #pragma unroll
    for (int ki = 0; ki < FS; ki++) {
        const float4* row = &xsh[base + ki * SST];
        float4 xw[4];
        xw[0] = row[0]; xw[1] = row[1]; xw[2] = row[2];
        #pragma unroll
        for (int kj = 0; kj < FS; kj++) {
            if (kj < 9) xw[(kj + 3) & 3] = row[kj + 3];   // compile-time guard
            #pragma unroll
            for (int r = 0; r < R; r++) {
                float4 X = xw[(kj + r) & 3];
                float s = fmaf(p0[r], X.x,
                          fmaf(p1[r], X.y,
                          fmaf(p2[r], X.z, p3[r] * X.w)));
                float e = ex2(s);       // psi pre-scaled by log2 e
                sum[r] += e;
                acc0[r] = fmaf(e, X.x, acc0[r]);
                acc1[r] = fmaf(e, X.y, acc1[r]);
                acc2[r] = fmaf(e, X.z, acc2[r]);
                acc3[r] = fmaf(e, X.w, acc3[r]);
            }
        }
    }

    // --- Epilogue: normalize, apply M, residual; float2 stores ---
    float a0[R], a1[R], a2[R], a3[R];
    #pragma unroll
    for (int r = 0; r < R; r++) {
        float inv = __frcp_rn(sum[r]);
        a0[r] = acc0[r] * inv;
        a1[r] = acc1[r] * inv;
        a2[r] = acc2[r] * inv;
        a3[r] = acc3[r] * inv;
    }
    float* ob = out + b * (C * HW);
    #pragma unroll
    for (int c = 0; c < C; c++) {
        float2 res;
        res.x = fmaf(wM[c*4+0], a0[0], fmaf(wM[c*4+1], a1[0], fmaf(wM[c*4+2], a2[0], wM[c*4+3] * a3[0]))) + xs[c][0];
        res.y = fmaf(wM[c*4+0], a0[1], fmaf(wM[c*4+1], a1[1], fmaf(wM[c*4+2], a2[1], wM[c*4+3] * a3[1]))) + xs[c][1];
        *(float2*)(ob + c * HW + pixbase) = res;
    }
}

// ---------------------------------------------------------------------------
extern "C" void kernel_launch(void* const* d_in, const int* in_sizes, int n_in,
                              void* d_out, int out_size)
{
    const float* x  = (const float*)d_in[0];
    const float* Wt = (const float*)d_in[1];
    const float* Wp = (const float*)d_in[2];
    const float* Wg = (const float*)d_in[3];
    const float* Ww = (const float*)d_in[4];
    float* out = (float*)d_out;

    dim3 grid(W / BW, H / BH, B);
    fused_kernel<<<grid, NTHREADS>>>(x, Wt, Wp, Wg, Ww, out);
}